// round 8
// baseline (speedup 1.0000x reference)
#include <cuda_runtime.h>
#include <cuda_fp16.h>
#include <cstdint>

// Problem dims (fixed by reference setup_inputs):
//   x:  [4, 2048, 4096] f32  -> M = 8192, K = 4096
//   wq: [4096, 4096] int32 (int8 values), group scales every 64 elems row-major
//   out: [8192, 4096] f32
#define MDIM 8192
#define NDIM 4096
#define KDIM 4096

// GEMM tile (both paths use this CTA tile footprint / grid)
#define BM 128
#define BN 256
#define BK 64
#define NTHREADS 256
#define KTILES (KDIM / BK)   // 64

// ---------------------------------------------------------------------------
// Path select: tcgen05 is only legal on arch-specific targets (sm_103a/f).
// The harness build includes a baseline compute_103 pass, which must also
// compile — it gets an mma.sync (HMMA) fallback body for the SAME kernel
// symbol. The driver runs whichever cubin matches the device best.
// ---------------------------------------------------------------------------
#if !defined(__CUDA_ARCH__)
#define TC_PATH 1   // host pass: either branch is syntactically fine; pick fast
#elif defined(__CUDA_ARCH_FEAT_SM103_ALL) || defined(__CUDA_ARCH_FEAT_SM100_ALL) || \
      (defined(__CUDA_ARCH_FAMILY_SPECIFIC__) && (__CUDA_ARCH_FAMILY_SPECIFIC__ >= 1000))
#define TC_PATH 1   // arch/family-specific device pass: tcgen05 available
#else
#define TC_PATH 0   // baseline device pass: mma.sync fallback
#endif

// ---------------------------------------------------------------------------
// Scratch: fp16 copies of x and dequantized W (device globals: no allocation)
// ---------------------------------------------------------------------------
__device__ __half g_Xh[(size_t)MDIM * KDIM];   // 64 MB
__device__ __half g_Wh[(size_t)NDIM * KDIM];   // 32 MB

// ---------------------------------------------------------------------------
// Common helpers
// ---------------------------------------------------------------------------
__device__ __forceinline__ uint32_t smem_u32(const void* p) {
    uint32_t a;
    asm("{ .reg .u64 t; cvta.to.shared.u64 t, %1; cvt.u32.u64 %0, t; }"
        : "=r"(a) : "l"(p));
    return a;
}

#define STS128(addr, v) \
    asm volatile("st.shared.v4.b32 [%0], {%1, %2, %3, %4};" \
                 :: "r"(addr), "r"((v).x), "r"((v).y), "r"((v).z), "r"((v).w) : "memory")

#define SWZ128(off) ((off) ^ (((off) >> 3) & 0x70))

// SMEM map for tcgen05 path (fallback needs far less; same allocation reused):
//   [0:4)      tmem base ptr
//   [8:24)     mbar[2]
//   [1024:...) A stages: 2 x (128 rows x 128 B) = 32 KB
//   [33792:..) B stages: 2 x (256 rows x 128 B) = 64 KB
#define SMEM_A      1024
#define SMEM_A_SZ   (BM * 128)                  // 16384
#define SMEM_B      (SMEM_A + 2 * SMEM_A_SZ)    // 33792 (1024-aligned)
#define SMEM_B_SZ   (BN * 128)                  // 32768
#define SMEM_TOTAL  (SMEM_B + 2 * SMEM_B_SZ)    // 99328

// ---------------------------------------------------------------------------
// Kernel 1: x f32 -> f16
// ---------------------------------------------------------------------------
__global__ void k_convert_x(const float* __restrict__ x) {
    size_t i = (size_t)blockIdx.x * blockDim.x + threadIdx.x;  // float4 index
    const size_t n4 = (size_t)MDIM * KDIM / 4;
    if (i >= n4) return;
    float4 v = reinterpret_cast<const float4*>(x)[i];
    __half2 h0 = __floats2half2_rn(v.x, v.y);
    __half2 h1 = __floats2half2_rn(v.z, v.w);
    uint2 o;
    o.x = *reinterpret_cast<uint32_t*>(&h0);
    o.y = *reinterpret_cast<uint32_t*>(&h1);
    reinterpret_cast<uint2*>(g_Xh)[i] = o;
}

// ---------------------------------------------------------------------------
// Kernel 2: grouped int8 dequant -> f16
// weight_quant flat index f: scale = weight_scale[f / 64]
// ---------------------------------------------------------------------------
__global__ void k_dequant_w(const int* __restrict__ q, const float* __restrict__ sc) {
    size_t i = (size_t)blockIdx.x * blockDim.x + threadIdx.x;  // int4 index (4 elems)
    const size_t n4 = (size_t)NDIM * KDIM / 4;
    if (i >= n4) return;
    int4 v = reinterpret_cast<const int4*>(q)[i];
    float s = __ldg(sc + (i >> 4));   // 16 int4-chunks per 64-elem group
    __half2 h0 = __floats2half2_rn((float)v.x * s, (float)v.y * s);
    __half2 h1 = __floats2half2_rn((float)v.z * s, (float)v.w * s);
    uint2 o;
    o.x = *reinterpret_cast<uint32_t*>(&h0);
    o.y = *reinterpret_cast<uint32_t*>(&h1);
    reinterpret_cast<uint2*>(g_Wh)[i] = o;
}

// ===========================================================================
// GEMM  out[M,N] = Xh[M,K] @ Wh[N,K]^T + bias
// ===========================================================================
#if TC_PATH
// ---------------------------------------------------------------------------
// tcgen05 path: cg1 f16 SS MMA, 128x256x64 CTA tile, 2-stage double buffer.
// ---------------------------------------------------------------------------
__device__ __forceinline__ uint32_t elect_one() {
    uint32_t pred;
    asm volatile(
        "{\n\t.reg .pred p;\n\t"
        "elect.sync _|p, 0xFFFFFFFF;\n\t"
        "selp.b32 %0, 1, 0, p;\n\t}"
        : "=r"(pred));
    return pred;
}

#define MBARRIER_INIT(addr, cnt) \
    asm volatile("mbarrier.init.shared.b64 [%0], %1;" :: "r"((uint32_t)(addr)), "r"((uint32_t)(cnt)) : "memory")

#define MBARRIER_WAIT_PARITY(addr, parity) do {                                   \
    uint32_t _m = (uint32_t)(addr);                                               \
    uint32_t _p = (uint32_t)(parity);                                             \
    uint32_t _done;                                                               \
    asm volatile(                                                                 \
        "{\n\t.reg .pred p;\n\t"                                                  \
        "mbarrier.try_wait.parity.acquire.cta.shared::cta.b64 p, [%1], %2;\n\t"   \
        "selp.b32 %0, 1, 0, p;\n\t}"                                              \
        : "=r"(_done) : "r"(_m), "r"(_p) : "memory");                             \
    if (!_done) {                                                                 \
        asm volatile(                                                             \
            "{\n\t.reg .pred P1;\n\t"                                             \
            "WL_%=:\n\t"                                                          \
            "mbarrier.try_wait.parity.acquire.cta.shared::cta.b64 P1, [%0], %1, 0x989680;\n\t" \
            "@P1 bra.uni WD_%=;\n\t"                                              \
            "bra.uni WL_%=;\n\t"                                                  \
            "WD_%=:\n\t}"                                                         \
            :: "r"(_m), "r"(_p) : "memory");                                      \
    }                                                                             \
} while (0)

#define TCGEN05_ALLOC(smem_addr, ncols) \
    asm volatile("tcgen05.alloc.cta_group::1.sync.aligned.shared::cta.b32 [%0], %1;" \
                 :: "r"((uint32_t)(smem_addr)), "r"((uint32_t)(ncols)) : "memory")
#define TCGEN05_DEALLOC(tmem, ncols) \
    asm volatile("tcgen05.dealloc.cta_group::1.sync.aligned.b32 %0, %1;" \
                 :: "r"(tmem), "r"((uint32_t)(ncols)))
#define TCGEN05_RELINQ() \
    asm volatile("tcgen05.relinquish_alloc_permit.cta_group::1.sync.aligned;")
#define TCGEN05_COMMIT(mbar) \
    asm volatile("tcgen05.commit.cta_group::1.mbarrier::arrive::one.shared::cluster.b64 [%0];" \
                 :: "r"((uint32_t)(mbar)) : "memory")
#define TCGEN05_FENCE_BEFORE() asm volatile("tcgen05.fence::before_thread_sync;" ::: "memory")
#define TCGEN05_FENCE_AFTER()  asm volatile("tcgen05.fence::after_thread_sync;" ::: "memory")
#define TCGEN05_WAIT_LD()      asm volatile("tcgen05.wait::ld.sync.aligned;" ::: "memory")
#define FENCE_ASYNC_SHARED()   asm volatile("fence.proxy.async.shared::cta;" ::: "memory")

#define TCGEN05_LD_X32(r, tmem_addr) \
    asm volatile( \
        "tcgen05.ld.sync.aligned.32x32b.x32.b32 " \
        "{%0, %1, %2, %3, %4, %5, %6, %7, " \
        " %8, %9, %10, %11, %12, %13, %14, %15, " \
        " %16, %17, %18, %19, %20, %21, %22, %23, " \
        " %24, %25, %26, %27, %28, %29, %30, %31}, [%32];" \
        : "=r"((r)[0]),  "=r"((r)[1]),  "=r"((r)[2]),  "=r"((r)[3]), \
          "=r"((r)[4]),  "=r"((r)[5]),  "=r"((r)[6]),  "=r"((r)[7]), \
          "=r"((r)[8]),  "=r"((r)[9]),  "=r"((r)[10]), "=r"((r)[11]), \
          "=r"((r)[12]), "=r"((r)[13]), "=r"((r)[14]), "=r"((r)[15]), \
          "=r"((r)[16]), "=r"((r)[17]), "=r"((r)[18]), "=r"((r)[19]), \
          "=r"((r)[20]), "=r"((r)[21]), "=r"((r)[22]), "=r"((r)[23]), \
          "=r"((r)[24]), "=r"((r)[25]), "=r"((r)[26]), "=r"((r)[27]), \
          "=r"((r)[28]), "=r"((r)[29]), "=r"((r)[30]), "=r"((r)[31]) \
        : "r"(tmem_addr))

// SW128 K-major descriptor: layout=2 (SW128), version=1, SBO=64, LBO=1
static __device__ __forceinline__ uint64_t make_desc_sw128(uint32_t addr) {
    return ((uint64_t)2 << 61) | ((uint64_t)1 << 46) | ((uint64_t)64 << 32) |
           ((uint64_t)1 << 16) | ((uint64_t)(addr >> 4) & 0x3FFF);
}

// idesc, kind::f16: c=F32 (bit4), a=FP16 (0), b=FP16 (0), no trans, N=256, M=128
#define MMA_IDESC ((1u << 4) | ((BN / 8u) << 17) | ((BM / 16u) << 24))

// SS-mode cg1 f16 MMA
__device__ __forceinline__ void mma_f16_ss(uint32_t d_tmem, uint64_t ad, uint64_t bd,
                                           uint32_t idesc, bool acc) {
    uint32_t en = acc ? 1u : 0u;
    asm volatile(
        "{\n\t.reg .pred p;\n\t"
        "setp.ne.u32 p, %5, 0;\n\t"
        "tcgen05.mma.cta_group::1.kind::f16 [%0], %1, %2, %3, {%4, %4, %4, %4}, p;\n\t"
        "}"
        :: "r"(d_tmem), "l"(ad), "l"(bd), "r"(idesc), "r"(0u), "r"(en)
        : "memory");
}

__global__ void __launch_bounds__(NTHREADS, 2)
k_gemm(const float* __restrict__ bias, float* __restrict__ out) {
    extern __shared__ char smem[];
    const uint32_t sb = smem_u32(smem);
    const int tid = threadIdx.x;
    const int wid = tid >> 5;
    const int lid = tid & 31;

    const int n0 = blockIdx.x * BN;   // 16 n-tiles
    const int m0 = blockIdx.y * BM;   // 64 m-tiles

    // TMEM alloc (warp 0, collective) + mbarrier init
    if (wid == 0) TCGEN05_ALLOC(sb + 0, 256);
    if (tid == 0) { MBARRIER_INIT(sb + 8, 1); MBARRIER_INIT(sb + 16, 1); }
    __syncthreads();
    uint32_t tmem;
    asm volatile("ld.shared.b32 %0, [%1];" : "=r"(tmem) : "r"(sb + 0));

    const __half* gA = g_Xh + (size_t)m0 * KDIM;
    const __half* gB = g_Wh + (size_t)n0 * KDIM;

    int ph[2] = {0, 0};

    for (int kt = 0; kt < KTILES; kt++) {
        const int s = kt & 1;
        if (kt >= 2) {   // wait until MMA(kt-2) has drained this buffer
            MBARRIER_WAIT_PARITY(sb + 8 + s * 8, ph[s] & 1);
            ph[s]++;
        }
        const uint32_t As = sb + SMEM_A + s * SMEM_A_SZ;
        const uint32_t Bs = sb + SMEM_B + s * SMEM_B_SZ;
        const int k0 = kt * BK;

        // A tile: 128 rows x 128 B = 1024 x 16B chunks, 4 per thread
#pragma unroll
        for (int i = 0; i < 4; i++) {
            const int c = tid + i * NTHREADS;
            const int row = c >> 3, col = c & 7;
            uint4 v = *reinterpret_cast<const uint4*>(gA + (size_t)row * KDIM + k0 + col * 8);
            uint32_t off = (uint32_t)(row * 128 + col * 16);
            STS128(As + SWZ128(off), v);
        }
        // B tile: 256 rows x 128 B = 2048 x 16B chunks, 8 per thread
#pragma unroll
        for (int i = 0; i < 8; i++) {
            const int c = tid + i * NTHREADS;
            const int row = c >> 3, col = c & 7;
            uint4 v = *reinterpret_cast<const uint4*>(gB + (size_t)row * KDIM + k0 + col * 8);
            uint32_t off = (uint32_t)(row * 128 + col * 16);
            STS128(Bs + SWZ128(off), v);
        }
        __syncthreads();

        if (wid == 0) {
            FENCE_ASYNC_SHARED();   // generic STS -> async-proxy MMA reads
            if (elect_one()) {
                const uint64_t ad = make_desc_sw128(As);
                const uint64_t bd = make_desc_sw128(Bs);
#pragma unroll
                for (int ks = 0; ks < 4; ks++)   // 4 x K=16 per BK=64
                    mma_f16_ss(tmem, ad + ks * 2, bd + ks * 2, MMA_IDESC,
                               (kt > 0) || (ks > 0));
                TCGEN05_COMMIT(sb + 8 + s * 8);
            }
        }
    }

    // All MMAs committed in-order; waiting on the last buffer's mbarrier
    // (kt = KTILES-1, s = 1) covers everything.
    MBARRIER_WAIT_PARITY(sb + 16, ph[1] & 1);
    TCGEN05_FENCE_AFTER();

    // Epilogue: warp (w&3) owns TMEM lane group (w&3)*32+lid; warps 4-7 take
    // columns 128..255, warps 0-3 take 0..127.
    const int colbase = (wid >= 4) ? 128 : 0;
    const int rowg = (wid & 3) * 32 + lid;
    float* orow = out + (size_t)(m0 + rowg) * NDIM + n0;

#pragma unroll
    for (int b = 0; b < 4; b++) {
        uint32_t d[32];
        TCGEN05_LD_X32(d, tmem + colbase + b * 32);
        TCGEN05_WAIT_LD();
#pragma unroll
        for (int j = 0; j < 32; j += 4) {
            const int c = colbase + b * 32 + j;
            float4 bv = __ldg(reinterpret_cast<const float4*>(bias + n0 + c));
            float4 v;
            v.x = __uint_as_float(d[j + 0]) + bv.x;
            v.y = __uint_as_float(d[j + 1]) + bv.y;
            v.z = __uint_as_float(d[j + 2]) + bv.z;
            v.w = __uint_as_float(d[j + 3]) + bv.w;
            *reinterpret_cast<float4*>(orow + c) = v;
        }
    }
    TCGEN05_FENCE_BEFORE();
    __syncthreads();
    if (wid == 0) {
        TCGEN05_RELINQ();
        TCGEN05_DEALLOC(tmem, 256);
    }
}

#else  // !TC_PATH ---------------------------------------------------------
// Fallback path (baseline compute_103 target): mma.sync.aligned.m16n8k16
// HMMA GEMM. Same grid: CTA tile 128x256 processed as two 128x128 sub-GEMMs.
// BK=32 SMEM staging, 40-half row pitch (conflict-free for fragment loads).
// 8 warps as 2(m) x 4(n); warp tile 64x32; acc 4x4 m16n8 fragments.
#define FBK       32
#define FPITCH    40                           // halves per smem row
#define FA_OFF    0
#define FB_OFF    (128 * FPITCH)               // halves

__device__ __forceinline__ void mma16816(float* c, const uint32_t* a, const uint32_t* b) {
    asm volatile(
        "mma.sync.aligned.m16n8k16.row.col.f32.f16.f16.f32 "
        "{%0,%1,%2,%3}, {%4,%5,%6,%7}, {%8,%9}, {%0,%1,%2,%3};"
        : "+f"(c[0]), "+f"(c[1]), "+f"(c[2]), "+f"(c[3])
        : "r"(a[0]), "r"(a[1]), "r"(a[2]), "r"(a[3]), "r"(b[0]), "r"(b[1]));
}

__global__ void __launch_bounds__(NTHREADS, 1)
k_gemm(const float* __restrict__ bias, float* __restrict__ out) {
    extern __shared__ char smem[];
    __half* sh = reinterpret_cast<__half*>(smem);
    const int tid = threadIdx.x;
    const int wid = tid >> 5, lid = tid & 31;
    const int n0 = blockIdx.x * BN;
    const int m0 = blockIdx.y * BM;
    const int warp_m = wid >> 2;        // 0..1 -> m offset *64
    const int warp_n = wid & 3;         // 0..3 -> n offset *32
    const int lrow = lid >> 2;          // 0..7
    const int lcol = lid & 3;           // 0..3

    for (int nh = 0; nh < 2; nh++) {
        const int n1 = n0 + nh * 128;
        const __half* gA = g_Xh + (size_t)m0 * KDIM;
        const __half* gB = g_Wh + (size_t)n1 * KDIM;

        float acc[4][4][4];
#pragma unroll
        for (int mi = 0; mi < 4; mi++)
#pragma unroll
            for (int ni = 0; ni < 4; ni++)
#pragma unroll
                for (int r = 0; r < 4; r++) acc[mi][ni][r] = 0.f;

        for (int k0 = 0; k0 < KDIM; k0 += FBK) {
            __syncthreads();   // previous iteration's fragment reads done
            // A tile: 128 rows x 32 halves = 512 x 16B chunks, 2 per thread
#pragma unroll
            for (int i = 0; i < 2; i++) {
                const int c = tid + i * NTHREADS;
                const int row = c >> 2, c4 = c & 3;
                uint4 v = *reinterpret_cast<const uint4*>(gA + (size_t)row * KDIM + k0 + c4 * 8);
                *reinterpret_cast<uint4*>(sh + FA_OFF + row * FPITCH + c4 * 8) = v;
            }
            // B tile: 128 rows x 32 halves
#pragma unroll
            for (int i = 0; i < 2; i++) {
                const int c = tid + i * NTHREADS;
                const int row = c >> 2, c4 = c & 3;
                uint4 v = *reinterpret_cast<const uint4*>(gB + (size_t)row * KDIM + k0 + c4 * 8);
                *reinterpret_cast<uint4*>(sh + FB_OFF + row * FPITCH + c4 * 8) = v;
            }
            __syncthreads();

#pragma unroll
            for (int kk = 0; kk < 2; kk++) {   // two k16 slabs per BK=32
                const int kb = kk * 16;
                uint32_t a[4][4], b[4][2];
#pragma unroll
                for (int mi = 0; mi < 4; mi++) {
                    const int rb = warp_m * 64 + mi * 16 + lrow;
                    const __half* p0 = sh + FA_OFF + rb * FPITCH + kb + lcol * 2;
                    const __half* p1 = sh + FA_OFF + (rb + 8) * FPITCH + kb + lcol * 2;
                    a[mi][0] = *reinterpret_cast<const uint32_t*>(p0);
                    a[mi][1] = *reinterpret_cast<const uint32_t*>(p1);
                    a[mi][2] = *reinterpret_cast<const uint32_t*>(p0 + 8);
                    a[mi][3] = *reinterpret_cast<const uint32_t*>(p1 + 8);
                }
#pragma unroll
                for (int ni = 0; ni < 4; ni++) {
                    const int nr = warp_n * 32 + ni * 8 + lrow;
                    const __half* p = sh + FB_OFF + nr * FPITCH + kb + lcol * 2;
                    b[ni][0] = *reinterpret_cast<const uint32_t*>(p);
                    b[ni][1] = *reinterpret_cast<const uint32_t*>(p + 8);
                }
#pragma unroll
                for (int mi = 0; mi < 4; mi++)
#pragma unroll
                    for (int ni = 0; ni < 4; ni++)
                        mma16816(acc[mi][ni], a[mi], b[ni]);
            }
        }

        // Epilogue: D frag (row=lrow, col=lcol*2) / (+8 rows for d2,d3)
#pragma unroll
        for (int mi = 0; mi < 4; mi++) {
            const int r0 = m0 + warp_m * 64 + mi * 16 + lrow;
#pragma unroll
            for (int ni = 0; ni < 4; ni++) {
                const int c0 = n1 + warp_n * 32 + ni * 8 + lcol * 2;
                const float b0 = bias[c0], b1 = bias[c0 + 1];
                float2 v0 = {acc[mi][ni][0] + b0, acc[mi][ni][1] + b1};
                float2 v1 = {acc[mi][ni][2] + b0, acc[mi][ni][3] + b1};
                *reinterpret_cast<float2*>(out + (size_t)r0 * NDIM + c0) = v0;
                *reinterpret_cast<float2*>(out + (size_t)(r0 + 8) * NDIM + c0) = v1;
            }
        }
        __syncthreads();   // smem reuse by next nh
    }
}
#endif  // TC_PATH

// ---------------------------------------------------------------------------
// Launch
// ---------------------------------------------------------------------------
extern "C" void kernel_launch(void* const* d_in, const int* in_sizes, int n_in,
                              void* d_out, int out_size) {
    const float* x    = (const float*)d_in[0];
    const int*   wq   = (const int*)d_in[1];
    const float* wsc  = (const float*)d_in[2];
    const float* bias = (const float*)d_in[3];
    float* out = (float*)d_out;

    (void)in_sizes; (void)n_in; (void)out_size;

    cudaFuncSetAttribute(k_gemm, cudaFuncAttributeMaxDynamicSharedMemorySize,
                         SMEM_TOTAL);

    {   // x -> fp16
        const size_t n4 = (size_t)MDIM * KDIM / 4;
        k_convert_x<<<(unsigned)((n4 + 255) / 256), 256>>>(x);
    }
    {   // w dequant -> fp16
        const size_t n4 = (size_t)NDIM * KDIM / 4;
        k_dequant_w<<<(unsigned)((n4 + 255) / 256), 256>>>(wq, wsc);
    }
    {   // GEMM
        dim3 grid(NDIM / BN, MDIM / BM);   // (16, 64)
        k_gemm<<<grid, NTHREADS, SMEM_TOTAL>>>(bias, out);
    }
}

// round 17
// speedup vs baseline: 1.1220x; 1.1220x over previous
#include <cuda_runtime.h>
#include <cuda_fp16.h>
#include <cstdint>

// Problem dims (fixed by reference setup_inputs):
//   x:  [4, 2048, 4096] f32  -> M = 8192, K = 4096
//   wq: [4096, 4096] int32 (int8 values), group scales every 64 elems row-major
//        group size 64 is K-contiguous -> one scale per (row, BK=64 slab)
//   out: [8192, 4096] f32
#define MDIM 8192
#define NDIM 4096
#define KDIM 4096

// GEMM tile: 256x256 CTA tile, BK=64, 3-stage pipeline, 512 threads.
#define BM 256
#define BN 256
#define BK 64
#define NTHREADS 512
#define KTILES (KDIM / BK)   // 64
#define STAGES 3

// ---------------------------------------------------------------------------
// Path select: tcgen05 only legal on arch-specific targets (sm_103a/f); the
// baseline compute_103 pass gets an mma.sync fallback body for the same symbol.
// ---------------------------------------------------------------------------
#if !defined(__CUDA_ARCH__)
#define TC_PATH 1
#elif defined(__CUDA_ARCH_FEAT_SM103_ALL) || defined(__CUDA_ARCH_FEAT_SM100_ALL) || \
      (defined(__CUDA_ARCH_FAMILY_SPECIFIC__) && (__CUDA_ARCH_FAMILY_SPECIFIC__ >= 1000))
#define TC_PATH 1
#else
#define TC_PATH 0
#endif

// ---------------------------------------------------------------------------
// Scratch (device globals: no allocation): fp16 x, packed int8 W.
// ---------------------------------------------------------------------------
__device__ __half       g_Xh[(size_t)MDIM * KDIM];   // 64 MB
__device__ signed char  g_Wq[(size_t)NDIM * KDIM];   // 16 MB

// ---------------------------------------------------------------------------
// Common helpers
// ---------------------------------------------------------------------------
__device__ __forceinline__ uint32_t smem_u32(const void* p) {
    uint32_t a;
    asm("{ .reg .u64 t; cvta.to.shared.u64 t, %1; cvt.u32.u64 %0, t; }"
        : "=r"(a) : "l"(p));
    return a;
}

#define STS128(addr, v) \
    asm volatile("st.shared.v4.b32 [%0], {%1, %2, %3, %4};" \
                 :: "r"(addr), "r"((v).x), "r"((v).y), "r"((v).z), "r"((v).w) : "memory")

#define SWZ128(off) ((off) ^ (((off) >> 3) & 0x70))

// SMEM map:
//   [0:4)       tmem base ptr
//   [16:16+24)  mbar[STAGES]
//   [1024:...)  A stages: 3 x (256 rows x 128 B) = 96 KB
//   [99328:...) B stages: 3 x (256 rows x 128 B) = 96 KB
#define SMEM_A      1024
#define SMEM_A_SZ   (BM * 128)                         // 32768
#define SMEM_B      (SMEM_A + STAGES * SMEM_A_SZ)      // 99328 (1024-aligned)
#define SMEM_B_SZ   (BN * 128)                         // 32768
#define SMEM_TOTAL  (SMEM_B + STAGES * SMEM_B_SZ)      // 197632 (193 KB)

// Convert 16 int8 (as uint4) -> 8 x half2 scaled by s.
__device__ __forceinline__ void dequant16(uint4 w, float s, uint32_t o[8]) {
    uint32_t ws[4] = {w.x, w.y, w.z, w.w};
#pragma unroll
    for (int j = 0; j < 4; j++) {
        int b0 = (int)(signed char)(ws[j] & 0xFF);
        int b1 = (int)(signed char)((ws[j] >> 8) & 0xFF);
        int b2 = (int)(signed char)((ws[j] >> 16) & 0xFF);
        int b3 = (int)(signed char)(ws[j] >> 24);
        __half2 h0 = __floats2half2_rn((float)b0 * s, (float)b1 * s);
        __half2 h1 = __floats2half2_rn((float)b2 * s, (float)b3 * s);
        o[j * 2 + 0] = *reinterpret_cast<uint32_t*>(&h0);
        o[j * 2 + 1] = *reinterpret_cast<uint32_t*>(&h1);
    }
}

// ---------------------------------------------------------------------------
// Kernel 1: x f32 -> f16
// ---------------------------------------------------------------------------
__global__ void k_convert_x(const float* __restrict__ x) {
    size_t i = (size_t)blockIdx.x * blockDim.x + threadIdx.x;  // float4 index
    const size_t n4 = (size_t)MDIM * KDIM / 4;
    if (i >= n4) return;
    float4 v = reinterpret_cast<const float4*>(x)[i];
    __half2 h0 = __floats2half2_rn(v.x, v.y);
    __half2 h1 = __floats2half2_rn(v.z, v.w);
    uint2 o;
    o.x = *reinterpret_cast<uint32_t*>(&h0);
    o.y = *reinterpret_cast<uint32_t*>(&h1);
    reinterpret_cast<uint2*>(g_Xh)[i] = o;
}

// ---------------------------------------------------------------------------
// Kernel 2: pack weight int32 -> int8 (values already in [-127,127]).
// Scales are applied in the GEMM loader (group = one BK slab per row).
// ---------------------------------------------------------------------------
__global__ void k_pack_w(const int* __restrict__ q) {
    size_t i = (size_t)blockIdx.x * blockDim.x + threadIdx.x;  // 16 elems/thread
    const size_t n16 = (size_t)NDIM * KDIM / 16;
    if (i >= n16) return;
    const int4* qp = reinterpret_cast<const int4*>(q) + i * 4;
    uint32_t o[4];
#pragma unroll
    for (int j = 0; j < 4; j++) {
        int4 v = qp[j];
        o[j] = (uint32_t)(v.x & 0xFF) | ((uint32_t)(v.y & 0xFF) << 8) |
               ((uint32_t)(v.z & 0xFF) << 16) | ((uint32_t)v.w << 24);
    }
    reinterpret_cast<uint4*>(g_Wq)[i] = make_uint4(o[0], o[1], o[2], o[3]);
}

// ===========================================================================
// GEMM  out[M,N] = Xh[M,K] @ dequant(Wq)[N,K]^T + bias
// ===========================================================================
#if TC_PATH
// ---------------------------------------------------------------------------
// tcgen05 path: 256x256 CTA tile = two cg1 M=128,N=256 f16 SS MMAs into
// TMEM cols [0,256) and [256,512). 3-stage SMEM pipeline, fused B dequant.
// ---------------------------------------------------------------------------
__device__ __forceinline__ uint32_t elect_one() {
    uint32_t pred;
    asm volatile(
        "{\n\t.reg .pred p;\n\t"
        "elect.sync _|p, 0xFFFFFFFF;\n\t"
        "selp.b32 %0, 1, 0, p;\n\t}"
        : "=r"(pred));
    return pred;
}

#define MBARRIER_INIT(addr, cnt) \
    asm volatile("mbarrier.init.shared.b64 [%0], %1;" :: "r"((uint32_t)(addr)), "r"((uint32_t)(cnt)) : "memory")

#define MBARRIER_WAIT_PARITY(addr, parity) do {                                   \
    uint32_t _m = (uint32_t)(addr);                                               \
    uint32_t _p = (uint32_t)(parity);                                             \
    uint32_t _done;                                                               \
    asm volatile(                                                                 \
        "{\n\t.reg .pred p;\n\t"                                                  \
        "mbarrier.try_wait.parity.acquire.cta.shared::cta.b64 p, [%1], %2;\n\t"   \
        "selp.b32 %0, 1, 0, p;\n\t}"                                              \
        : "=r"(_done) : "r"(_m), "r"(_p) : "memory");                             \
    if (!_done) {                                                                 \
        asm volatile(                                                             \
            "{\n\t.reg .pred P1;\n\t"                                             \
            "WL_%=:\n\t"                                                          \
            "mbarrier.try_wait.parity.acquire.cta.shared::cta.b64 P1, [%0], %1, 0x989680;\n\t" \
            "@P1 bra.uni WD_%=;\n\t"                                              \
            "bra.uni WL_%=;\n\t"                                                  \
            "WD_%=:\n\t}"                                                         \
            :: "r"(_m), "r"(_p) : "memory");                                      \
    }                                                                             \
} while (0)

#define TCGEN05_ALLOC(smem_addr, ncols) \
    asm volatile("tcgen05.alloc.cta_group::1.sync.aligned.shared::cta.b32 [%0], %1;" \
                 :: "r"((uint32_t)(smem_addr)), "r"((uint32_t)(ncols)) : "memory")
#define TCGEN05_DEALLOC(tmem, ncols) \
    asm volatile("tcgen05.dealloc.cta_group::1.sync.aligned.b32 %0, %1;" \
                 :: "r"(tmem), "r"((uint32_t)(ncols)))
#define TCGEN05_RELINQ() \
    asm volatile("tcgen05.relinquish_alloc_permit.cta_group::1.sync.aligned;")
#define TCGEN05_COMMIT(mbar) \
    asm volatile("tcgen05.commit.cta_group::1.mbarrier::arrive::one.shared::cluster.b64 [%0];" \
                 :: "r"((uint32_t)(mbar)) : "memory")
#define TCGEN05_FENCE_BEFORE() asm volatile("tcgen05.fence::before_thread_sync;" ::: "memory")
#define TCGEN05_FENCE_AFTER()  asm volatile("tcgen05.fence::after_thread_sync;" ::: "memory")
#define TCGEN05_WAIT_LD()      asm volatile("tcgen05.wait::ld.sync.aligned;" ::: "memory")
#define FENCE_ASYNC_SHARED()   asm volatile("fence.proxy.async.shared::cta;" ::: "memory")

#define TCGEN05_LD_X32(r, tmem_addr) \
    asm volatile( \
        "tcgen05.ld.sync.aligned.32x32b.x32.b32 " \
        "{%0, %1, %2, %3, %4, %5, %6, %7, " \
        " %8, %9, %10, %11, %12, %13, %14, %15, " \
        " %16, %17, %18, %19, %20, %21, %22, %23, " \
        " %24, %25, %26, %27, %28, %29, %30, %31}, [%32];" \
        : "=r"((r)[0]),  "=r"((r)[1]),  "=r"((r)[2]),  "=r"((r)[3]), \
          "=r"((r)[4]),  "=r"((r)[5]),  "=r"((r)[6]),  "=r"((r)[7]), \
          "=r"((r)[8]),  "=r"((r)[9]),  "=r"((r)[10]), "=r"((r)[11]), \
          "=r"((r)[12]), "=r"((r)[13]), "=r"((r)[14]), "=r"((r)[15]), \
          "=r"((r)[16]), "=r"((r)[17]), "=r"((r)[18]), "=r"((r)[19]), \
          "=r"((r)[20]), "=r"((r)[21]), "=r"((r)[22]), "=r"((r)[23]), \
          "=r"((r)[24]), "=r"((r)[25]), "=r"((r)[26]), "=r"((r)[27]), \
          "=r"((r)[28]), "=r"((r)[29]), "=r"((r)[30]), "=r"((r)[31]) \
        : "r"(tmem_addr))

// SW128 K-major descriptor: layout=2 (SW128), version=1, SBO=64, LBO=1
static __device__ __forceinline__ uint64_t make_desc_sw128(uint32_t addr) {
    return ((uint64_t)2 << 61) | ((uint64_t)1 << 46) | ((uint64_t)64 << 32) |
           ((uint64_t)1 << 16) | ((uint64_t)(addr >> 4) & 0x3FFF);
}

// idesc, kind::f16: c=F32 (bit4), a=FP16, b=FP16, no trans, N=256, M=128
// (validated in the R8 passing kernel)
#define MMA_IDESC ((1u << 4) | ((256u / 8u) << 17) | ((128u / 16u) << 24))

__device__ __forceinline__ void mma_f16_ss(uint32_t d_tmem, uint64_t ad, uint64_t bd,
                                           uint32_t idesc, bool acc) {
    uint32_t en = acc ? 1u : 0u;
    asm volatile(
        "{\n\t.reg .pred p;\n\t"
        "setp.ne.u32 p, %5, 0;\n\t"
        "tcgen05.mma.cta_group::1.kind::f16 [%0], %1, %2, %3, {%4, %4, %4, %4}, p;\n\t"
        "}"
        :: "r"(d_tmem), "l"(ad), "l"(bd), "r"(idesc), "r"(0u), "r"(en)
        : "memory");
}

__global__ void __launch_bounds__(NTHREADS, 1)
k_gemm(const float* __restrict__ wsc, const float* __restrict__ bias,
       float* __restrict__ out) {
    extern __shared__ char smem[];
    const uint32_t sb = smem_u32(smem);
    const int tid = threadIdx.x;
    const int wid = tid >> 5;
    const int lid = tid & 31;

    const int n0 = blockIdx.x * BN;   // 16 n-tiles
    const int m0 = blockIdx.y * BM;   // 32 m-tiles

    if (wid == 0) TCGEN05_ALLOC(sb + 0, 512);
    if (tid == 0) {
#pragma unroll
        for (int s = 0; s < STAGES; s++) MBARRIER_INIT(sb + 16 + s * 8, 1);
    }
    __syncthreads();
    uint32_t tmem;
    asm volatile("ld.shared.b32 %0, [%1];" : "=r"(tmem) : "r"(sb + 0));

    const __half* gA = g_Xh + (size_t)m0 * KDIM;
    const signed char* gB = g_Wq + (size_t)n0 * KDIM;
    const float* gS = wsc + (size_t)n0 * (KDIM / 64);   // 64 scales per row

    int ph[STAGES] = {0, 0, 0};
    int s = 0;

    for (int kt = 0; kt < KTILES; kt++) {
        if (kt >= STAGES) {   // wait until MMA(kt-STAGES) drained this buffer
            MBARRIER_WAIT_PARITY(sb + 16 + s * 8, ph[s] & 1);
            ph[s]++;
        }
        const uint32_t As = sb + SMEM_A + s * SMEM_A_SZ;
        const uint32_t Bs = sb + SMEM_B + s * SMEM_B_SZ;
        const int k0 = kt * BK;

        // A tile: 256 rows x 128 B = 2048 x 16B chunks, 4 per thread
#pragma unroll
        for (int i = 0; i < 4; i++) {
            const int c = tid + i * NTHREADS;
            const int row = c >> 3, col = c & 7;
            uint4 v = *reinterpret_cast<const uint4*>(gA + (size_t)row * KDIM + k0 + col * 8);
            STS128(As + SWZ128((uint32_t)(row * 128 + col * 16)), v);
        }
        // B tile: 256 rows x 64 int8 = 1024 x 16B chunks, 2 per thread,
        // dequant to f16 (one scale per row per BK slab) -> 32 B out each.
#pragma unroll
        for (int i = 0; i < 2; i++) {
            const int c = tid + i * NTHREADS;
            const int row = c >> 2, kc = c & 3;
            uint4 w = *reinterpret_cast<const uint4*>(gB + (size_t)row * KDIM + k0 + kc * 16);
            float sc = __ldg(gS + row * (KDIM / 64) + kt);
            uint32_t o[8];
            dequant16(w, sc, o);
            uint32_t off = (uint32_t)(row * 128 + kc * 32);
            uint4 v0 = make_uint4(o[0], o[1], o[2], o[3]);
            uint4 v1 = make_uint4(o[4], o[5], o[6], o[7]);
            STS128(Bs + SWZ128(off), v0);
            STS128(Bs + SWZ128(off + 16), v1);
        }
        __syncthreads();

        if (wid == 0) {
            FENCE_ASYNC_SHARED();
            if (elect_one()) {
                const uint64_t ad0 = make_desc_sw128(As);
                const uint64_t ad1 = make_desc_sw128(As + 128 * 128);  // M half 1
                const uint64_t bd  = make_desc_sw128(Bs);
#pragma unroll
                for (int ks = 0; ks < 4; ks++) {   // 4 x K=16 per BK=64
                    const bool acc = (kt > 0) || (ks > 0);
                    mma_f16_ss(tmem,       ad0 + ks * 2, bd + ks * 2, MMA_IDESC, acc);
                    mma_f16_ss(tmem + 256, ad1 + ks * 2, bd + ks * 2, MMA_IDESC, acc);
                }
                TCGEN05_COMMIT(sb + 16 + s * 8);
            }
        }
        s = (s == STAGES - 1) ? 0 : s + 1;
    }

    // Final commit was on stage (KTILES-1) % STAGES; commits are in-order.
    {
        const int sl = (KTILES - 1) % STAGES;
        MBARRIER_WAIT_PARITY(sb + 16 + sl * 8, ph[sl] & 1);
    }
    TCGEN05_FENCE_AFTER();

    // Epilogue: 16 warps. mhalf selects M-half (TMEM col base 0/256),
    // chalf selects 128-col half within it; subpartition = (wid&3).
    const int mhalf = (wid >> 2) & 1;
    const int chalf = wid >> 3;
    const int rowg = (wid & 3) * 32 + lid;
    const int tcol0 = mhalf * 256 + chalf * 128;
    // orow already includes the chalf*128 column offset — do NOT re-add it.
    float* orow = out + (size_t)(m0 + mhalf * 128 + rowg) * NDIM + n0 + chalf * 128;

#pragma unroll
    for (int b = 0; b < 4; b++) {
        uint32_t d[32];
        TCGEN05_LD_X32(d, tmem + tcol0 + b * 32);
        TCGEN05_WAIT_LD();
#pragma unroll
        for (int j = 0; j < 32; j += 4) {
            const int c = chalf * 128 + b * 32 + j;   // column within BN (bias idx)
            float4 bv = __ldg(reinterpret_cast<const float4*>(bias + n0 + c));
            float4 v;
            v.x = __uint_as_float(d[j + 0]) + bv.x;
            v.y = __uint_as_float(d[j + 1]) + bv.y;
            v.z = __uint_as_float(d[j + 2]) + bv.z;
            v.w = __uint_as_float(d[j + 3]) + bv.w;
            *reinterpret_cast<float4*>(orow + b * 32 + j) = v;
        }
    }
    TCGEN05_FENCE_BEFORE();
    __syncthreads();
    if (wid == 0) {
        TCGEN05_RELINQ();
        TCGEN05_DEALLOC(tmem, 512);
    }
}

#else  // !TC_PATH ---------------------------------------------------------
// Fallback (baseline compute_103): mma.sync m16n8k16 HMMA. Same launch
// config (grid (16,32), 512 threads). Processes the 256x256 tile as two
// 256x128 n-halves; 16 warps as 4(m) x 4(n), warp tile 64x32.
// Single-stage SMEM (stage-0 regions of the same layout), fused B dequant.
__device__ __forceinline__ void mma16816(float* c, const uint32_t* a, const uint32_t* b) {
    asm volatile(
        "mma.sync.aligned.m16n8k16.row.col.f32.f16.f16.f32 "
        "{%0,%1,%2,%3}, {%4,%5,%6,%7}, {%8,%9}, {%0,%1,%2,%3};"
        : "+f"(c[0]), "+f"(c[1]), "+f"(c[2]), "+f"(c[3])
        : "r"(a[0]), "r"(a[1]), "r"(a[2]), "r"(a[3]), "r"(b[0]), "r"(b[1]));
}

__global__ void __launch_bounds__(NTHREADS, 1)
k_gemm(const float* __restrict__ wsc, const float* __restrict__ bias,
       float* __restrict__ out) {
    extern __shared__ char smem[];
    const uint32_t As = smem_u32(smem) + SMEM_A;
    const uint32_t Bs = smem_u32(smem) + SMEM_B;
    const int tid = threadIdx.x;
    const int wid = tid >> 5, lid = tid & 31;
    const int n0 = blockIdx.x * BN;
    const int m0 = blockIdx.y * BM;
    const int warp_m = wid >> 2;        // 0..3 -> m offset *64
    const int warp_n = wid & 3;         // 0..3 -> n offset *32
    const int lrow = lid >> 2;          // 0..7
    const int lcol = lid & 3;           // 0..3

    const __half* gA = g_Xh + (size_t)m0 * KDIM;

    for (int nh = 0; nh < 2; nh++) {
        const int n1 = n0 + nh * 128;
        const signed char* gB = g_Wq + (size_t)n1 * KDIM;
        const float* gS = wsc + (size_t)n1 * (KDIM / 64);

        float acc[4][4][4];
#pragma unroll
        for (int mi = 0; mi < 4; mi++)
#pragma unroll
            for (int ni = 0; ni < 4; ni++)
#pragma unroll
                for (int r = 0; r < 4; r++) acc[mi][ni][r] = 0.f;

        for (int kt = 0; kt < KTILES; kt++) {
            const int k0 = kt * BK;
            __syncthreads();
            // A: 256 rows x 128 B = 2048 chunks, 4/thread
#pragma unroll
            for (int i = 0; i < 4; i++) {
                const int c = tid + i * NTHREADS;
                const int row = c >> 3, col = c & 7;
                uint4 v = *reinterpret_cast<const uint4*>(gA + (size_t)row * KDIM + k0 + col * 8);
                STS128(As + SWZ128((uint32_t)(row * 128 + col * 16)), v);
            }
            // B: 128 rows x 64 int8 = 512 chunks, 1/thread, dequant
            {
                const int row = tid >> 2, kc = tid & 3;
                uint4 w = *reinterpret_cast<const uint4*>(gB + (size_t)row * KDIM + k0 + kc * 16);
                float sc = __ldg(gS + row * (KDIM / 64) + kt);
                uint32_t o[8];
                dequant16(w, sc, o);
                uint32_t off = (uint32_t)(row * 128 + kc * 32);
                uint4 v0 = make_uint4(o[0], o[1], o[2], o[3]);
                uint4 v1 = make_uint4(o[4], o[5], o[6], o[7]);
                STS128(Bs + SWZ128(off), v0);
                STS128(Bs + SWZ128(off + 16), v1);
            }
            __syncthreads();

#pragma unroll
            for (int kk = 0; kk < 4; kk++) {   // 4 k16 slabs per BK=64
                const int kb = kk * 16;        // halves
                uint32_t a[4][4], b[4][2];
#pragma unroll
                for (int mi = 0; mi < 4; mi++) {
                    const int rb = warp_m * 64 + mi * 16 + lrow;
                    const uint32_t base0 = (uint32_t)(rb * 128 + (kb + lcol * 2) * 2);
                    const uint32_t base1 = (uint32_t)((rb + 8) * 128 + (kb + lcol * 2) * 2);
                    asm volatile("ld.shared.b32 %0, [%1];" : "=r"(a[mi][0]) : "r"(As + SWZ128(base0)));
                    asm volatile("ld.shared.b32 %0, [%1];" : "=r"(a[mi][1]) : "r"(As + SWZ128(base1)));
                    asm volatile("ld.shared.b32 %0, [%1];" : "=r"(a[mi][2]) : "r"(As + SWZ128(base0 + 16)));
                    asm volatile("ld.shared.b32 %0, [%1];" : "=r"(a[mi][3]) : "r"(As + SWZ128(base1 + 16)));
                }
#pragma unroll
                for (int ni = 0; ni < 4; ni++) {
                    const int nr = warp_n * 32 + ni * 8 + lrow;
                    const uint32_t base = (uint32_t)(nr * 128 + (kb + lcol * 2) * 2);
                    asm volatile("ld.shared.b32 %0, [%1];" : "=r"(b[ni][0]) : "r"(Bs + SWZ128(base)));
                    asm volatile("ld.shared.b32 %0, [%1];" : "=r"(b[ni][1]) : "r"(Bs + SWZ128(base + 16)));
                }
#pragma unroll
                for (int mi = 0; mi < 4; mi++)
#pragma unroll
                    for (int ni = 0; ni < 4; ni++)
                        mma16816(acc[mi][ni], a[mi], b[ni]);
            }
        }

#pragma unroll
        for (int mi = 0; mi < 4; mi++) {
            const int r0 = m0 + warp_m * 64 + mi * 16 + lrow;
#pragma unroll
            for (int ni = 0; ni < 4; ni++) {
                const int c0 = n1 + warp_n * 32 + ni * 8 + lcol * 2;
                const float b0 = bias[c0], b1 = bias[c0 + 1];
                float2 v0 = {acc[mi][ni][0] + b0, acc[mi][ni][1] + b1};
                float2 v1 = {acc[mi][ni][2] + b0, acc[mi][ni][3] + b1};
                *reinterpret_cast<float2*>(out + (size_t)r0 * NDIM + c0) = v0;
                *reinterpret_cast<float2*>(out + (size_t)(r0 + 8) * NDIM + c0) = v1;
            }
        }
        __syncthreads();
    }
}
#endif  // TC_PATH

// ---------------------------------------------------------------------------
// Launch
// ---------------------------------------------------------------------------
extern "C" void kernel_launch(void* const* d_in, const int* in_sizes, int n_in,
                              void* d_out, int out_size) {
    const float* x    = (const float*)d_in[0];
    const int*   wq   = (const int*)d_in[1];
    const float* wsc  = (const float*)d_in[2];
    const float* bias = (const float*)d_in[3];
    float* out = (float*)d_out;

    (void)in_sizes; (void)n_in; (void)out_size;

    cudaFuncSetAttribute(k_gemm, cudaFuncAttributeMaxDynamicSharedMemorySize,
                         SMEM_TOTAL);

    {   // x -> fp16
        const size_t n4 = (size_t)MDIM * KDIM / 4;
        k_convert_x<<<(unsigned)((n4 + 255) / 256), 256>>>(x);
    }
    {   // w int32 -> packed int8
        const size_t n16 = (size_t)NDIM * KDIM / 16;
        k_pack_w<<<(unsigned)((n16 + 255) / 256), 256>>>(wq);
    }
    {   // GEMM (fused dequant)
        dim3 grid(NDIM / BN, MDIM / BM);   // (16, 32)
        k_gemm<<<grid, NTHREADS, SMEM_TOTAL>>>(wsc, bias, out);
    }
}